// round 9
// baseline (speedup 1.0000x reference)
#include <cuda_runtime.h>
#include <cstdint>

// ---------------------------------------------------------------------------
// AlignedMPNN: B=8, N=256, F=128, D=128
// Output: ret [8,256,128] followed by et [8,256,256,128]
// ---------------------------------------------------------------------------

#define Bq 8
#define Nn 256
#define Ff 128
#define Dd 128
#define M_ET (Bq * Nn * Nn)          // 524288
#define NROWS (Bq * (Nn + 1))        // 2056
#define N_TILES2 (M_ET / 256)        // 2048 tiles of 256 rows

// scratch for MPNN chain
__device__ float g_msg1[NROWS * Dd];
__device__ float g_msg2[NROWS * Dd];
__device__ float g_o1[NROWS * Dd];

// ===========================================================================
// helpers
// ===========================================================================
__device__ __forceinline__ uint32_t smem_u32_of(const void* p) {
    uint32_t a;
    asm("{ .reg .u64 t; cvta.to.shared.u64 t, %1; cvt.u32.u64 %0, t; }" : "=r"(a) : "l"(p));
    return a;
}

#define STS128(a0, a1, a2, a3, addr) \
    asm volatile("st.shared.v4.b32 [%0], {%1, %2, %3, %4};" :: "r"(addr), "r"(a0), "r"(a1), "r"(a2), "r"(a3) : "memory")

#define LDS128F(v, addr) \
    asm volatile("ld.shared.v4.f32 {%0, %1, %2, %3}, [%4];" \
        : "=f"((v).x), "=f"((v).y), "=f"((v).z), "=f"((v).w) : "r"(addr))

#define LDSM4(r, addr) \
    asm volatile("ldmatrix.sync.aligned.m8n8.x4.shared.b16 {%0,%1,%2,%3}, [%4];" \
        : "=r"((r)[0]), "=r"((r)[1]), "=r"((r)[2]), "=r"((r)[3]) : "r"(addr))

#define LDSM2(r, addr) \
    asm volatile("ldmatrix.sync.aligned.m8n8.x2.shared.b16 {%0,%1}, [%2];" \
        : "=r"((r)[0]), "=r"((r)[1]) : "r"(addr))

#define MMA_F16(d, a, b) \
    asm volatile("mma.sync.aligned.m16n8k16.row.col.f32.f16.f16.f32 " \
        "{%0,%1,%2,%3}, {%4,%5,%6,%7}, {%8,%9}, {%0,%1,%2,%3};" \
        : "+f"((d)[0]), "+f"((d)[1]), "+f"((d)[2]), "+f"((d)[3]) \
        : "r"((a)[0]), "r"((a)[1]), "r"((a)[2]), "r"((a)[3]), "r"((b)[0]), "r"((b)[1]))

__device__ __forceinline__ void cp_async16(uint32_t dst, const void* src) {
    asm volatile("cp.async.cg.shared.global [%0], [%1], 16;"
                 :: "r"(dst), "l"(__cvta_generic_to_global(src)) : "memory");
}
#define CP_COMMIT() asm volatile("cp.async.commit_group;" ::: "memory")
#define CP_WAIT2()  asm volatile("cp.async.wait_group 2;" ::: "memory")

// named producer/consumer barriers (576 = all threads participate per phase)
#define BAR_SYNC(id)   asm volatile("bar.sync %0, 576;"   :: "r"(id) : "memory")
#define BAR_ARRIVE(id) asm volatile("bar.arrive %0, 576;" :: "r"(id) : "memory")

// f16 tile layout: 64B rows, unit u (0..3, 16B), XOR swizzle. (verified R6)
#define ASWZ64(r, u) ((uint32_t)((r) * 64 + (((u) ^ (((r) >> 1) & 3)) * 16)))

// pack two f32 -> f16x2 (x0 in low half)
__device__ __forceinline__ uint32_t cvt2h(float x0, float x1) {
    uint32_t r;
    asm("cvt.rn.f16x2.f32 %0, %1, %2;" : "=r"(r) : "f"(x1), "f"(x0));
    return r;
}

// ===========================================================================
// et GEMM: C[M,128] = A1[M,128k] @ W[0:128,:] + A2[M,128k] @ W[128:256,:] + be
// Warp-specialized: 148 persistent CTAs x 576 threads.
//   warps 0-15: consumers (ldsm + HMMA only), warp grid 4x4, 64x32 tiles
//   warps 16-17: producers (cp.async f32 ring -> cvt f16 -> STS f16 bufs)
// M-tile 256, k-chunks of 32. Named barriers: FULL=1+buf, EMPTY=3+buf.
//
// smem (192KB):
//   [0      .. 65536)  W fp16: 8 k32-chunks (8KB each), ASWZ64 rows
//   [65536  .. 98304)  A f16: 2 bufs x 16KB (256 rows x 64B), ASWZ64
//   [98304  .. 196608) A f32 stage: 3 x 32KB (256 rows x 128B, XOR units)
// ===========================================================================
#define OFF_F16 65536
#define OFF_F32 98304
#define SMEM_ET 196608

__global__ __launch_bounds__(576, 1)
void et_mma_kernel(const float* __restrict__ A1,
                   const float* __restrict__ A2,
                   const float* __restrict__ W,     // [256,128] f32
                   const float* __restrict__ bias,  // [128]
                   float* __restrict__ C)           // [M,128]
{
    extern __shared__ char smem[];
    const uint32_t sb = smem_u32_of(smem);
    const int tid  = threadIdx.x;
    const int lane = tid & 31;
    const int wid  = tid >> 5;

    // ---- one-time W conversion into resident smem (fp16, [n][k]) ----
    if (tid < 512) {
        const int n = tid & 127;
        const int g = tid >> 7;                 // 0..3
#pragma unroll
        for (int t = 0; t < 8; ++t) {
            const int kk = g * 8 + t;           // 8-k unit index 0..31
            const int c  = kk >> 2;
            const int u  = kk & 3;
            float w[8];
#pragma unroll
            for (int j = 0; j < 8; ++j) w[j] = W[(kk * 8 + j) * 128 + n];
            uint32_t p0 = cvt2h(w[0], w[1]);
            uint32_t p1 = cvt2h(w[2], w[3]);
            uint32_t p2 = cvt2h(w[4], w[5]);
            uint32_t p3 = cvt2h(w[6], w[7]);
            STS128(p0, p1, p2, p3, sb + c * 8192 + ASWZ64(n, u));
        }
    }
    __syncthreads();

    if (wid < 16) {
        // =================== CONSUMER: ldsm + MMA only ===================
        const int warpM = wid >> 2;      // 0..3
        const int warpN = wid & 3;       // 0..3

        const int mat  = lane >> 3;
        const int row0 = warpM * 64 + (mat & 1) * 8 + (lane & 7);
        const int ah   = mat >> 1;
        const int xr   = (row0 >> 1) & 3;
        uint32_t aoffs[2];
#pragma unroll
        for (int s = 0; s < 2; ++s)
            aoffs[s] = (uint32_t)(row0 * 64 + (((2 * s + ah) ^ xr) * 16));

        const int ls = lane & 15;
        const int n0 = warpN * 32 + (ls & 7);
        const int ub = ls >> 3;
        const int xn = (n0 >> 1) & 3;
        uint32_t boffs[2];
#pragma unroll
        for (int s = 0; s < 2; ++s)
            boffs[s] = (uint32_t)(n0 * 64 + (((2 * s + ub) ^ xn) * 16));

        float2 biasv[4];
#pragma unroll
        for (int nt = 0; nt < 4; ++nt)
            biasv[nt] = *(const float2*)&bias[warpN * 32 + nt * 8 + (lane & 3) * 2];

        int tile = blockIdx.x;
        int g = 0;
        while (tile < N_TILES2) {
            float acc[4][4][4];
#pragma unroll
            for (int mt = 0; mt < 4; ++mt)
#pragma unroll
                for (int nt = 0; nt < 4; ++nt) {
                    acc[mt][nt][0] = biasv[nt].x; acc[mt][nt][1] = biasv[nt].y;
                    acc[mt][nt][2] = biasv[nt].x; acc[mt][nt][3] = biasv[nt].y;
                }

#pragma unroll 1
            for (int c = 0; c < 8; ++c, ++g) {
                const int buf = g & 1;
                BAR_SYNC(1 + buf);                       // wait producers: f16 buf full
                const uint32_t wb = sb + (uint32_t)(c * 8192);
                const uint32_t ab = sb + OFF_F16 + buf * 16384;
#pragma unroll
                for (int s = 0; s < 2; ++s) {
                    uint32_t Av[4][4], Bv[4][2];
#pragma unroll
                    for (int mt = 0; mt < 4; ++mt) LDSM4(Av[mt], ab + aoffs[s] + mt * 1024);
#pragma unroll
                    for (int nt = 0; nt < 4; ++nt) LDSM2(Bv[nt], wb + boffs[s] + nt * 512);
#pragma unroll
                    for (int mt = 0; mt < 4; ++mt)
#pragma unroll
                        for (int nt = 0; nt < 4; ++nt) MMA_F16(acc[mt][nt], Av[mt], Bv[nt]);
                }
                BAR_ARRIVE(3 + buf);                     // release buf to producers
            }

            // epilogue (overlaps with producers filling next tile)
            const size_t m0 = (size_t)tile * 256;
#pragma unroll
            for (int mt = 0; mt < 4; ++mt) {
                const size_t r0 = m0 + warpM * 64 + mt * 16 + (lane >> 2);
#pragma unroll
                for (int nt = 0; nt < 4; ++nt) {
                    const int col = warpN * 32 + nt * 8 + (lane & 3) * 2;
                    *(float2*)&C[r0 * 128 + col]       = make_float2(acc[mt][nt][0], acc[mt][nt][1]);
                    *(float2*)&C[(r0 + 8) * 128 + col] = make_float2(acc[mt][nt][2], acc[mt][nt][3]);
                }
            }
            tile += gridDim.x;
        }
    } else {
        // =================== PRODUCER: load + convert ===================
        const int pt = tid - 512;        // 0..63, owns rows pt*4 .. pt*4+3

        // per-row f32 stage unit offsets (XOR by row&7, conflict-free LDS/STS)
        // prologue: issue chunks 0,1 of first tile
        int tile = blockIdx.x;
#pragma unroll
        for (int pc = 0; pc < 2; ++pc) {
            const uint32_t st = sb + OFF_F32 + pc * 32768;
#pragma unroll
            for (int rr = 0; rr < 4; ++rr) {
                const int r = pt * 4 + rr;
                const float* p = A1 + (size_t)tile * 32768 + r * 128 + pc * 32;
                const uint32_t d = st + r * 128;
#pragma unroll
                for (int u = 0; u < 8; ++u)
                    cp_async16(d + ((u ^ (r & 7)) * 16), p + u * 4);
            }
            CP_COMMIT();
        }

        int g = 0;
        while (tile < N_TILES2) {
#pragma unroll 1
            for (int c = 0; c < 8; ++c, ++g) {
                // issue chunk g+2
                {
                    int nt2 = tile, nc2 = c + 2;
                    if (nc2 >= 8) { nc2 -= 8; nt2 += gridDim.x; }
                    if (nt2 < N_TILES2) {
                        const float* base = (nc2 < 4) ? A1 : A2;
                        const uint32_t st = sb + OFF_F32 + ((g + 2) % 3) * 32768;
#pragma unroll
                        for (int rr = 0; rr < 4; ++rr) {
                            const int r = pt * 4 + rr;
                            const float* p = base + (size_t)nt2 * 32768 + r * 128 + (nc2 & 3) * 32;
                            const uint32_t d = st + r * 128;
#pragma unroll
                            for (int u = 0; u < 8; ++u)
                                cp_async16(d + ((u ^ (r & 7)) * 16), p + u * 4);
                        }
                    }
                    CP_COMMIT();
                }
                CP_WAIT2();                          // chunk g's f32 data ready

                const int buf = g & 1;
                if (g >= 2) BAR_SYNC(3 + buf);       // wait consumers freed buf

                // convert 4 rows: f32 stage -> f16 buf
                const uint32_t s32 = sb + OFF_F32 + (g % 3) * 32768;
                const uint32_t fb  = sb + OFF_F16 + buf * 16384;
#pragma unroll
                for (int rr = 0; rr < 4; ++rr) {
                    const int r = pt * 4 + rr;
                    const uint32_t srow = s32 + r * 128;
                    float4 v[8];
#pragma unroll
                    for (int u = 0; u < 8; ++u) LDS128F(v[u], srow + ((u ^ (r & 7)) * 16));
#pragma unroll
                    for (int uu = 0; uu < 4; ++uu) {
                        uint32_t q0 = cvt2h(v[2 * uu].x, v[2 * uu].y);
                        uint32_t q1 = cvt2h(v[2 * uu].z, v[2 * uu].w);
                        uint32_t q2 = cvt2h(v[2 * uu + 1].x, v[2 * uu + 1].y);
                        uint32_t q3 = cvt2h(v[2 * uu + 1].z, v[2 * uu + 1].w);
                        STS128(q0, q1, q2, q3, fb + ASWZ64(r, uu));
                    }
                }
                BAR_ARRIVE(1 + buf);                 // f16 buf full
            }
            tile += gridDim.x;
        }
    }
}

// ===========================================================================
// Kernel 2: msg1/msg2/o1 = nt @ {W_m1,W_m2,W_o1} + bias.
// ===========================================================================
__global__ __launch_bounds__(512)
void msgs_gemm_kernel(const float* __restrict__ node,
                      const float* __restrict__ hidden,
                      const float* __restrict__ Wm1, const float* __restrict__ bm1,
                      const float* __restrict__ Wm2, const float* __restrict__ bm2,
                      const float* __restrict__ Wo1, const float* __restrict__ bo1)
{
    __shared__ float s[8][2 * Ff];
    __shared__ float part[3][3][8][128];
    const int r0  = blockIdx.x * 8;
    const int tid = threadIdx.x;
    const int col = tid & 127;
    const int kq  = tid >> 7;

    for (int t = tid; t < 8 * 256; t += 512) {
        const int r = t >> 8, k = t & 255;
        const int rowi = r0 + r;
        const int b = rowi / (Nn + 1);
        const int i = rowi % (Nn + 1);
        float v = 0.f;
        if (i < Nn)
            v = (k < Ff) ? node[(b * Nn + i) * Ff + k]
                         : hidden[(b * Nn + i) * Ff + (k - Ff)];
        s[r][k] = v;
    }
    __syncthreads();

    float a1[8], a2[8], a3[8];
#pragma unroll
    for (int r = 0; r < 8; ++r) { a1[r] = 0.f; a2[r] = 0.f; a3[r] = 0.f; }

    const int kbase = kq * 64;
#pragma unroll 4
    for (int kk = 0; kk < 64; ++kk) {
        const int k = kbase + kk;
        const float w1 = Wm1[k * Dd + col];
        const float w2 = Wm2[k * Dd + col];
        const float w3 = Wo1[k * Dd + col];
#pragma unroll
        for (int r = 0; r < 8; ++r) {
            const float sv = s[r][k];
            a1[r] = fmaf(sv, w1, a1[r]);
            a2[r] = fmaf(sv, w2, a2[r]);
            a3[r] = fmaf(sv, w3, a3[r]);
        }
    }

    if (kq) {
#pragma unroll
        for (int r = 0; r < 8; ++r) {
            part[kq - 1][0][r][col] = a1[r];
            part[kq - 1][1][r][col] = a2[r];
            part[kq - 1][2][r][col] = a3[r];
        }
    }
    __syncthreads();

    if (kq == 0) {
        const float bb1 = bm1[col], bb2 = bm2[col], bb3 = bo1[col];
#pragma unroll
        for (int r = 0; r < 8; ++r) {
            float o1 = a1[r] + bb1, o2 = a2[r] + bb2, o3 = a3[r] + bb3;
#pragma unroll
            for (int q = 0; q < 3; ++q) {
                o1 += part[q][0][r][col];
                o2 += part[q][1][r][col];
                o3 += part[q][2][r][col];
            }
            const int rowi = r0 + r;
            g_msg1[rowi * Dd + col] = o1;
            g_msg2[rowi * Dd + col] = o2;
            g_o1[rowi * Dd + col]   = o3;
        }
    }
}

// ===========================================================================
// Kernel 3 (fused): masked max + add msg1, then ret = o1 + msgs @ W_o2 + b_o2
// ===========================================================================
__global__ __launch_bounds__(256)
void maxfinal_kernel(const int* __restrict__ adj,
                     const float* __restrict__ Wo2,
                     const float* __restrict__ bo2,
                     float* __restrict__ out)      // [B*N,128]
{
    __shared__ int mask[Nn];
    __shared__ float red[2][4][128];
    __shared__ float ms[4][128];
    __shared__ float pg[4][128];
    const int blk = blockIdx.x;
    const int b   = blk >> 6;
    const int j0  = (blk & 63) * 4;
    const int tid = threadIdx.x;
    const int d   = tid & 127;
    const int ih  = tid >> 7;

    {
        const int* p = adj + ((size_t)(b * Nn + tid) * Nn + j0);
        const int4 a = *(const int4*)p;
        mask[tid] = (a.x > 0) | ((a.y > 0) << 1) | ((a.z > 0) << 2) | ((a.w > 0) << 3);
    }
    __syncthreads();

    const float* m2 = g_msg2 + (size_t)(b * (Nn + 1)) * Dd + d;
    const float vv = m2[Nn * Dd];
    float vj[4] = {vv, vv, vv, vv};

#pragma unroll 4
    for (int ii = 0; ii < 128; ++ii) {
        const int i = ih * 128 + ii;
        const float x = m2[i * Dd];
        const int mk = mask[i];
#pragma unroll
        for (int q = 0; q < 4; ++q)
            if (mk & (1 << q)) vj[q] = fmaxf(vj[q], x);
    }
#pragma unroll
    for (int q = 0; q < 4; ++q) red[ih][q][d] = vj[q];
    __syncthreads();

    if (ih == 0) {
#pragma unroll
        for (int q = 0; q < 4; ++q)
            ms[q][d] = g_msg1[(size_t)(b * (Nn + 1) + j0 + q) * Dd + d]
                     + fmaxf(red[0][q][d], red[1][q][d]);
    }
    __syncthreads();

    float acc[4] = {0.f, 0.f, 0.f, 0.f};
    const int kb = ih * 64;
#pragma unroll 4
    for (int kk = 0; kk < 64; ++kk) {
        const int k = kb + kk;
        const float w = Wo2[k * Dd + d];
#pragma unroll
        for (int q = 0; q < 4; ++q) acc[q] = fmaf(ms[q][k], w, acc[q]);
    }
    if (ih) {
#pragma unroll
        for (int q = 0; q < 4; ++q) pg[q][d] = acc[q];
    }
    __syncthreads();
    if (!ih) {
        const float bb = bo2[d];
#pragma unroll
        for (int q = 0; q < 4; ++q)
            out[(size_t)(b * Nn + j0 + q) * Dd + d] =
                acc[q] + pg[q][d] + g_o1[(size_t)(b * (Nn + 1) + j0 + q) * Dd + d] + bb;
    }
}

// ===========================================================================
extern "C" void kernel_launch(void* const* d_in, const int* in_sizes, int n_in,
                              void* d_out, int out_size)
{
    const float* node_fts = (const float*)d_in[0];
    const float* edge_fts = (const float*)d_in[1];
    const int*   adj_mat  = (const int*)d_in[3];
    const float* hidden   = (const float*)d_in[4];
    const float* e_hidden = (const float*)d_in[5];
    const float* We   = (const float*)d_in[6];
    const float* be   = (const float*)d_in[7];
    const float* W_m1 = (const float*)d_in[8];
    const float* b_m1 = (const float*)d_in[9];
    const float* W_m2 = (const float*)d_in[10];
    const float* b_m2 = (const float*)d_in[11];
    const float* W_o1 = (const float*)d_in[12];
    const float* b_o1 = (const float*)d_in[13];
    const float* W_o2 = (const float*)d_in[14];
    const float* b_o2 = (const float*)d_in[15];

    float* ret_out = (float*)d_out;
    float* et_out  = (float*)d_out + Bq * Nn * Dd;

    static cudaStream_t s_chain = nullptr;
    static cudaEvent_t ev_fork = nullptr, ev_join = nullptr;
    if (!s_chain) {
        cudaStreamCreateWithFlags(&s_chain, cudaStreamNonBlocking);
        cudaEventCreateWithFlags(&ev_fork, cudaEventDisableTiming);
        cudaEventCreateWithFlags(&ev_join, cudaEventDisableTiming);
        cudaFuncSetAttribute(et_mma_kernel, cudaFuncAttributeMaxDynamicSharedMemorySize, SMEM_ET);
    }

    // fork: MPNN chain runs concurrently with the big et GEMM
    cudaEventRecord(ev_fork, 0);
    cudaStreamWaitEvent(s_chain, ev_fork, 0);
    msgs_gemm_kernel<<<NROWS / 8, 512, 0, s_chain>>>(node_fts, hidden,
                                                     W_m1, b_m1, W_m2, b_m2, W_o1, b_o1);
    maxfinal_kernel<<<Bq * Nn / 4, 256, 0, s_chain>>>(adj_mat, W_o2, b_o2, ret_out);
    cudaEventRecord(ev_join, s_chain);

    // et GEMM (warp-specialized producer/consumer, fp16 mma)
    et_mma_kernel<<<148, 576, SMEM_ET>>>(edge_fts, e_hidden, We, be, et_out);

    // join
    cudaStreamWaitEvent(0, ev_join, 0);
}

// round 10
// speedup vs baseline: 1.5735x; 1.5735x over previous
#include <cuda_runtime.h>
#include <cstdint>

// ---------------------------------------------------------------------------
// AlignedMPNN: B=8, N=256, F=128, D=128
// Output: ret [8,256,128] followed by et [8,256,256,128]
// ---------------------------------------------------------------------------

#define Bq 8
#define Nn 256
#define Ff 128
#define Dd 128
#define M_ET (Bq * Nn * Nn)          // 524288
#define NROWS (Bq * (Nn + 1))        // 2056
#define N_TILES2 (M_ET / 256)        // 2048 tiles of 256 rows

// scratch for MPNN chain
__device__ float g_msg1[NROWS * Dd];
__device__ float g_msg2[NROWS * Dd];
__device__ float g_o1[NROWS * Dd];

// ===========================================================================
// helpers
// ===========================================================================
__device__ __forceinline__ uint32_t smem_u32_of(const void* p) {
    uint32_t a;
    asm("{ .reg .u64 t; cvta.to.shared.u64 t, %1; cvt.u32.u64 %0, t; }" : "=r"(a) : "l"(p));
    return a;
}

#define STS128(a0, a1, a2, a3, addr) \
    asm volatile("st.shared.v4.b32 [%0], {%1, %2, %3, %4};" :: "r"(addr), "r"(a0), "r"(a1), "r"(a2), "r"(a3) : "memory")

#define LDS128F(v, addr) \
    asm volatile("ld.shared.v4.f32 {%0, %1, %2, %3}, [%4];" \
        : "=f"((v).x), "=f"((v).y), "=f"((v).z), "=f"((v).w) : "r"(addr))

#define LDSM4(r, addr) \
    asm volatile("ldmatrix.sync.aligned.m8n8.x4.shared.b16 {%0,%1,%2,%3}, [%4];" \
        : "=r"((r)[0]), "=r"((r)[1]), "=r"((r)[2]), "=r"((r)[3]) : "r"(addr))

#define LDSM2(r, addr) \
    asm volatile("ldmatrix.sync.aligned.m8n8.x2.shared.b16 {%0,%1}, [%2];" \
        : "=r"((r)[0]), "=r"((r)[1]) : "r"(addr))

#define MMA_F16(d, a, b) \
    asm volatile("mma.sync.aligned.m16n8k16.row.col.f32.f16.f16.f32 " \
        "{%0,%1,%2,%3}, {%4,%5,%6,%7}, {%8,%9}, {%0,%1,%2,%3};" \
        : "+f"((d)[0]), "+f"((d)[1]), "+f"((d)[2]), "+f"((d)[3]) \
        : "r"((a)[0]), "r"((a)[1]), "r"((a)[2]), "r"((a)[3]), "r"((b)[0]), "r"((b)[1]))

__device__ __forceinline__ void cp_async16(uint32_t dst, const void* src) {
    asm volatile("cp.async.cg.shared.global [%0], [%1], 16;"
                 :: "r"(dst), "l"(__cvta_generic_to_global(src)) : "memory");
}
#define CP_COMMIT() asm volatile("cp.async.commit_group;" ::: "memory")
#define CP_WAIT2()  asm volatile("cp.async.wait_group 2;" ::: "memory")

// f16 tile layout: 64B rows, unit u (0..3, 16B), XOR swizzle. (verified R6)
#define ASWZ64(r, u) ((uint32_t)((r) * 64 + (((u) ^ (((r) >> 1) & 3)) * 16)))

// pack two f32 -> f16x2 (x0 in low half)
__device__ __forceinline__ uint32_t cvt2h(float x0, float x1) {
    uint32_t r;
    asm("cvt.rn.f16x2.f32 %0, %1, %2;" : "=r"(r) : "f"(x1), "f"(x0));
    return r;
}

// ===========================================================================
// et GEMM: C[M,128] = A1[M,128k] @ W[0:128,:] + A2[M,128k] @ W[128:256,:] + be
// mma.sync fp16 single-term; 148 persistent CTAs x 512 threads, 1 CTA/SM.
// M-tile 256, warp grid 4x4 (64x32/warp), k-chunks of 32.
//
// Software-pipelined regions, ONE barrier per chunk:
//   region g: cp.async(g+3) -> wait(g+1 ready) -> LDS f32(g+1)
//             -> ldsm+MMA(g) [buf g&1]  ||  cvt+STS(g+1) [buf (g+1)&1]
//             -> __syncthreads
// MMA and next-chunk convert coexist between barriers; convert latency
// hides under the ~2048-cyc tensor-pipe occupancy of the 512 HMMA.
//
// smem (192KB):
//   [0      .. 65536)  W fp16: 8 k32-chunks (8KB each), ASWZ64 rows
//   [65536  .. 98304)  A f16: 2 bufs x 16KB (256 rows x 64B), ASWZ64
//   [98304  .. 196608) A f32 stage: 3 x 32KB (256 rows x 128B, XOR units)
// ===========================================================================
#define OFF_F16 65536
#define OFF_F32 98304
#define SMEM_ET 196608

__global__ __launch_bounds__(512, 1)
void et_mma_kernel(const float* __restrict__ A1,
                   const float* __restrict__ A2,
                   const float* __restrict__ W,     // [256,128] f32
                   const float* __restrict__ bias,  // [128]
                   float* __restrict__ C)           // [M,128]
{
    extern __shared__ char smem[];
    const uint32_t sb = smem_u32_of(smem);
    const int tid   = threadIdx.x;
    const int lane  = tid & 31;
    const int wid   = tid >> 5;
    const int warpM = wid >> 2;      // 0..3
    const int warpN = wid & 3;       // 0..3

    // ---- one-time W conversion into resident smem (fp16, [n][k]) ----
    {
        const int n = tid & 127;
        const int g = tid >> 7;                 // 0..3
#pragma unroll
        for (int t = 0; t < 8; ++t) {
            const int kk = g * 8 + t;           // 8-k unit index 0..31
            const int c  = kk >> 2;
            const int u  = kk & 3;
            float w[8];
#pragma unroll
            for (int j = 0; j < 8; ++j) w[j] = W[(kk * 8 + j) * 128 + n];
            uint32_t p0 = cvt2h(w[0], w[1]);
            uint32_t p1 = cvt2h(w[2], w[3]);
            uint32_t p2 = cvt2h(w[4], w[5]);
            uint32_t p3 = cvt2h(w[6], w[7]);
            STS128(p0, p1, p2, p3, sb + c * 8192 + ASWZ64(n, u));
        }
    }

    // ---- per-thread invariant addressing ----
    const int mat  = lane >> 3;
    const int row0 = warpM * 64 + (mat & 1) * 8 + (lane & 7);
    const int ah   = mat >> 1;
    const int xr   = (row0 >> 1) & 3;
    uint32_t aoffs[2];
#pragma unroll
    for (int s = 0; s < 2; ++s)
        aoffs[s] = (uint32_t)(row0 * 64 + (((2 * s + ah) ^ xr) * 16));

    const int ls = lane & 15;
    const int n0 = warpN * 32 + (ls & 7);
    const int ub = ls >> 3;
    const int xn = (n0 >> 1) & 3;
    uint32_t boffs[2];
#pragma unroll
    for (int s = 0; s < 2; ++s)
        boffs[s] = (uint32_t)(n0 * 64 + (((2 * s + ub) ^ xn) * 16));

    float2 biasv[4];
#pragma unroll
    for (int nt = 0; nt < 4; ++nt)
        biasv[nt] = *(const float2*)&bias[warpN * 32 + nt * 8 + (lane & 3) * 2];

    // A staging: 2 threads per row; each thread owns 4 x 16B units of its row.
    const int row  = tid >> 1;
    const int half = tid & 1;
    const uint32_t f32row = (uint32_t)(OFF_F32 + row * 128);
    uint32_t fu[4];
#pragma unroll
    for (int q = 0; q < 4; ++q)
        fu[q] = (uint32_t)((((half * 4 + q) ^ (row & 7)) * 16));
    const uint32_t sa0 = (uint32_t)OFF_F16 + ASWZ64(row, half * 2);
    const uint32_t sa1 = (uint32_t)OFF_F16 + ASWZ64(row, half * 2 + 1);
    const int goff = row * 128 + half * 16;

    __syncthreads();

    int tile = blockIdx.x;

    // ---- prologue: issue chunks 0,1,2; convert chunk 0 -> f16 buf 0 ----
#pragma unroll
    for (int pc = 0; pc < 3; ++pc) {
        if (tile < N_TILES2) {
            const float* p = A1 + (size_t)tile * 32768 + goff + pc * 32;
            const uint32_t d = sb + f32row + pc * 32768;
#pragma unroll
            for (int q = 0; q < 4; ++q) cp_async16(d + fu[q], p + q * 4);
        }
        CP_COMMIT();
    }
    {
        CP_WAIT2();
        const uint32_t s32 = sb + f32row;     // stage 0
        float4 v0, v1, v2, v3;
        LDS128F(v0, s32 + fu[0]);
        LDS128F(v1, s32 + fu[1]);
        LDS128F(v2, s32 + fu[2]);
        LDS128F(v3, s32 + fu[3]);
        uint32_t p0 = cvt2h(v0.x, v0.y), p1 = cvt2h(v0.z, v0.w);
        uint32_t p2 = cvt2h(v1.x, v1.y), p3 = cvt2h(v1.z, v1.w);
        uint32_t p4 = cvt2h(v2.x, v2.y), p5 = cvt2h(v2.z, v2.w);
        uint32_t p6 = cvt2h(v3.x, v3.y), p7 = cvt2h(v3.z, v3.w);
        STS128(p0, p1, p2, p3, sb + sa0);     // buf 0
        STS128(p4, p5, p6, p7, sb + sa1);
    }
    __syncthreads();

    int g = 0;    // global chunk counter (chunk being MMA'd)

    while (tile < N_TILES2) {
        float acc[4][4][4];
#pragma unroll
        for (int mt = 0; mt < 4; ++mt)
#pragma unroll
            for (int nt = 0; nt < 4; ++nt) {
                acc[mt][nt][0] = biasv[nt].x; acc[mt][nt][1] = biasv[nt].y;
                acc[mt][nt][2] = biasv[nt].x; acc[mt][nt][3] = biasv[nt].y;
            }

#pragma unroll 1
        for (int c = 0; c < 8; ++c, ++g) {
            // 1) issue cp.async for chunk g+3 into stage g%3
            {
                int nt3 = tile, nc3 = c + 3;
                if (nc3 >= 8) { nc3 -= 8; nt3 += gridDim.x; }
                if (nt3 < N_TILES2) {
                    const float* base = (nc3 < 4) ? A1 : A2;
                    const float* p = base + (size_t)nt3 * 32768 + goff + (nc3 & 3) * 32;
                    const uint32_t d = sb + f32row + (g % 3) * 32768;
#pragma unroll
                    for (int q = 0; q < 4; ++q) cp_async16(d + fu[q], p + q * 4);
                }
                CP_COMMIT();
            }

            // 2) chunk g+1's f32 stage is ready; start its loads early
            CP_WAIT2();
            float4 v0, v1, v2, v3;
            {
                const uint32_t s32 = sb + f32row + ((g + 1) % 3) * 32768;
                LDS128F(v0, s32 + fu[0]);
                LDS128F(v1, s32 + fu[1]);
                LDS128F(v2, s32 + fu[2]);
                LDS128F(v3, s32 + fu[3]);
            }

            // 3) MMA chunk g from f16 buf g&1 (overlaps with convert below)
            const uint32_t wb = sb + (uint32_t)(c * 8192);
            const uint32_t ab = sb + OFF_F16 + (g & 1) * 16384;
#pragma unroll
            for (int s = 0; s < 2; ++s) {
                uint32_t Av[4][4], Bv[4][2];
#pragma unroll
                for (int mt = 0; mt < 4; ++mt) LDSM4(Av[mt], ab + aoffs[s] + mt * 1024);
#pragma unroll
                for (int nt = 0; nt < 4; ++nt) LDSM2(Bv[nt], wb + boffs[s] + nt * 512);
#pragma unroll
                for (int mt = 0; mt < 4; ++mt)
#pragma unroll
                    for (int nt = 0; nt < 4; ++nt) MMA_F16(acc[mt][nt], Av[mt], Bv[nt]);
            }

            // 4) convert chunk g+1 -> f16 buf (g+1)&1
            {
                uint32_t p0 = cvt2h(v0.x, v0.y), p1 = cvt2h(v0.z, v0.w);
                uint32_t p2 = cvt2h(v1.x, v1.y), p3 = cvt2h(v1.z, v1.w);
                uint32_t p4 = cvt2h(v2.x, v2.y), p5 = cvt2h(v2.z, v2.w);
                uint32_t p6 = cvt2h(v3.x, v3.y), p7 = cvt2h(v3.z, v3.w);
                const uint32_t fb = sb + ((g + 1) & 1) * 16384;
                STS128(p0, p1, p2, p3, fb + sa0);
                STS128(p4, p5, p6, p7, fb + sa1);
            }
            __syncthreads();
        }

        // epilogue: direct STG (32B-sector aligned float2 stores)
        const size_t m0 = (size_t)tile * 256;
#pragma unroll
        for (int mt = 0; mt < 4; ++mt) {
            const size_t r0 = m0 + warpM * 64 + mt * 16 + (lane >> 2);
#pragma unroll
            for (int nt = 0; nt < 4; ++nt) {
                const int col = warpN * 32 + nt * 8 + (lane & 3) * 2;
                *(float2*)&C[r0 * 128 + col]       = make_float2(acc[mt][nt][0], acc[mt][nt][1]);
                *(float2*)&C[(r0 + 8) * 128 + col] = make_float2(acc[mt][nt][2], acc[mt][nt][3]);
            }
        }
        tile += gridDim.x;
    }
}

// ===========================================================================
// Kernel 2: msg1/msg2/o1 = nt @ {W_m1,W_m2,W_o1} + bias.
// ===========================================================================
__global__ __launch_bounds__(512)
void msgs_gemm_kernel(const float* __restrict__ node,
                      const float* __restrict__ hidden,
                      const float* __restrict__ Wm1, const float* __restrict__ bm1,
                      const float* __restrict__ Wm2, const float* __restrict__ bm2,
                      const float* __restrict__ Wo1, const float* __restrict__ bo1)
{
    __shared__ float s[8][2 * Ff];
    __shared__ float part[3][3][8][128];
    const int r0  = blockIdx.x * 8;
    const int tid = threadIdx.x;
    const int col = tid & 127;
    const int kq  = tid >> 7;

    for (int t = tid; t < 8 * 256; t += 512) {
        const int r = t >> 8, k = t & 255;
        const int rowi = r0 + r;
        const int b = rowi / (Nn + 1);
        const int i = rowi % (Nn + 1);
        float v = 0.f;
        if (i < Nn)
            v = (k < Ff) ? node[(b * Nn + i) * Ff + k]
                         : hidden[(b * Nn + i) * Ff + (k - Ff)];
        s[r][k] = v;
    }
    __syncthreads();

    float a1[8], a2[8], a3[8];
#pragma unroll
    for (int r = 0; r < 8; ++r) { a1[r] = 0.f; a2[r] = 0.f; a3[r] = 0.f; }

    const int kbase = kq * 64;
#pragma unroll 4
    for (int kk = 0; kk < 64; ++kk) {
        const int k = kbase + kk;
        const float w1 = Wm1[k * Dd + col];
        const float w2 = Wm2[k * Dd + col];
        const float w3 = Wo1[k * Dd + col];
#pragma unroll
        for (int r = 0; r < 8; ++r) {
            const float sv = s[r][k];
            a1[r] = fmaf(sv, w1, a1[r]);
            a2[r] = fmaf(sv, w2, a2[r]);
            a3[r] = fmaf(sv, w3, a3[r]);
        }
    }

    if (kq) {
#pragma unroll
        for (int r = 0; r < 8; ++r) {
            part[kq - 1][0][r][col] = a1[r];
            part[kq - 1][1][r][col] = a2[r];
            part[kq - 1][2][r][col] = a3[r];
        }
    }
    __syncthreads();

    if (kq == 0) {
        const float bb1 = bm1[col], bb2 = bm2[col], bb3 = bo1[col];
#pragma unroll
        for (int r = 0; r < 8; ++r) {
            float o1 = a1[r] + bb1, o2 = a2[r] + bb2, o3 = a3[r] + bb3;
#pragma unroll
            for (int q = 0; q < 3; ++q) {
                o1 += part[q][0][r][col];
                o2 += part[q][1][r][col];
                o3 += part[q][2][r][col];
            }
            const int rowi = r0 + r;
            g_msg1[rowi * Dd + col] = o1;
            g_msg2[rowi * Dd + col] = o2;
            g_o1[rowi * Dd + col]   = o3;
        }
    }
}

// ===========================================================================
// Kernel 3 (fused): masked max + add msg1, then ret = o1 + msgs @ W_o2 + b_o2
// ===========================================================================
__global__ __launch_bounds__(256)
void maxfinal_kernel(const int* __restrict__ adj,
                     const float* __restrict__ Wo2,
                     const float* __restrict__ bo2,
                     float* __restrict__ out)      // [B*N,128]
{
    __shared__ int mask[Nn];
    __shared__ float red[2][4][128];
    __shared__ float ms[4][128];
    __shared__ float pg[4][128];
    const int blk = blockIdx.x;
    const int b   = blk >> 6;
    const int j0  = (blk & 63) * 4;
    const int tid = threadIdx.x;
    const int d   = tid & 127;
    const int ih  = tid >> 7;

    {
        const int* p = adj + ((size_t)(b * Nn + tid) * Nn + j0);
        const int4 a = *(const int4*)p;
        mask[tid] = (a.x > 0) | ((a.y > 0) << 1) | ((a.z > 0) << 2) | ((a.w > 0) << 3);
    }
    __syncthreads();

    const float* m2 = g_msg2 + (size_t)(b * (Nn + 1)) * Dd + d;
    const float vv = m2[Nn * Dd];
    float vj[4] = {vv, vv, vv, vv};

#pragma unroll 4
    for (int ii = 0; ii < 128; ++ii) {
        const int i = ih * 128 + ii;
        const float x = m2[i * Dd];
        const int mk = mask[i];
#pragma unroll
        for (int q = 0; q < 4; ++q)
            if (mk & (1 << q)) vj[q] = fmaxf(vj[q], x);
    }
#pragma unroll
    for (int q = 0; q < 4; ++q) red[ih][q][d] = vj[q];
    __syncthreads();

    if (ih == 0) {
#pragma unroll
        for (int q = 0; q < 4; ++q)
            ms[q][d] = g_msg1[(size_t)(b * (Nn + 1) + j0 + q) * Dd + d]
                     + fmaxf(red[0][q][d], red[1][q][d]);
    }
    __syncthreads();

    float acc[4] = {0.f, 0.f, 0.f, 0.f};
    const int kb = ih * 64;
#pragma unroll 4
    for (int kk = 0; kk < 64; ++kk) {
        const int k = kb + kk;
        const float w = Wo2[k * Dd + d];
#pragma unroll
        for (int q = 0; q < 4; ++q) acc[q] = fmaf(ms[q][k], w, acc[q]);
    }
    if (ih) {
#pragma unroll
        for (int q = 0; q < 4; ++q) pg[q][d] = acc[q];
    }
    __syncthreads();
    if (!ih) {
        const float bb = bo2[d];
#pragma unroll
        for (int q = 0; q < 4; ++q)
            out[(size_t)(b * Nn + j0 + q) * Dd + d] =
                acc[q] + pg[q][d] + g_o1[(size_t)(b * (Nn + 1) + j0 + q) * Dd + d] + bb;
    }
}

// ===========================================================================
extern "C" void kernel_launch(void* const* d_in, const int* in_sizes, int n_in,
                              void* d_out, int out_size)
{
    const float* node_fts = (const float*)d_in[0];
    const float* edge_fts = (const float*)d_in[1];
    const int*   adj_mat  = (const int*)d_in[3];
    const float* hidden   = (const float*)d_in[4];
    const float* e_hidden = (const float*)d_in[5];
    const float* We   = (const float*)d_in[6];
    const float* be   = (const float*)d_in[7];
    const float* W_m1 = (const float*)d_in[8];
    const float* b_m1 = (const float*)d_in[9];
    const float* W_m2 = (const float*)d_in[10];
    const float* b_m2 = (const float*)d_in[11];
    const float* W_o1 = (const float*)d_in[12];
    const float* b_o1 = (const float*)d_in[13];
    const float* W_o2 = (const float*)d_in[14];
    const float* b_o2 = (const float*)d_in[15];

    float* ret_out = (float*)d_out;
    float* et_out  = (float*)d_out + Bq * Nn * Dd;

    static cudaStream_t s_chain = nullptr;
    static cudaEvent_t ev_fork = nullptr, ev_join = nullptr;
    if (!s_chain) {
        cudaStreamCreateWithFlags(&s_chain, cudaStreamNonBlocking);
        cudaEventCreateWithFlags(&ev_fork, cudaEventDisableTiming);
        cudaEventCreateWithFlags(&ev_join, cudaEventDisableTiming);
        cudaFuncSetAttribute(et_mma_kernel, cudaFuncAttributeMaxDynamicSharedMemorySize, SMEM_ET);
    }

    // fork: MPNN chain runs concurrently with the big et GEMM
    cudaEventRecord(ev_fork, 0);
    cudaStreamWaitEvent(s_chain, ev_fork, 0);
    msgs_gemm_kernel<<<NROWS / 8, 512, 0, s_chain>>>(node_fts, hidden,
                                                     W_m1, b_m1, W_m2, b_m2, W_o1, b_o1);
    maxfinal_kernel<<<Bq * Nn / 4, 256, 0, s_chain>>>(adj_mat, W_o2, b_o2, ret_out);
    cudaEventRecord(ev_join, s_chain);

    // et GEMM (software-pipelined single-barrier regions, fp16 mma)
    et_mma_kernel<<<148, 512, SMEM_ET>>>(edge_fts, e_hidden, We, be, et_out);

    // join
    cudaStreamWaitEvent(0, ev_join, 0);
}

// round 11
// speedup vs baseline: 1.6518x; 1.0497x over previous
#include <cuda_runtime.h>
#include <cstdint>

// ---------------------------------------------------------------------------
// AlignedMPNN: B=8, N=256, F=128, D=128
// Output: ret [8,256,128] followed by et [8,256,256,128]
// ---------------------------------------------------------------------------

#define Bq 8
#define Nn 256
#define Ff 128
#define Dd 128
#define M_ET (Bq * Nn * Nn)          // 524288
#define NROWS (Bq * (Nn + 1))        // 2056
#define N_TILES2 (M_ET / 256)        // 2048 tiles of 256 rows

// scratch for MPNN chain
__device__ float g_msg1[NROWS * Dd];
__device__ float g_msg2[NROWS * Dd];
__device__ float g_o1[NROWS * Dd];

// ===========================================================================
// helpers
// ===========================================================================
__device__ __forceinline__ uint32_t smem_u32_of(const void* p) {
    uint32_t a;
    asm("{ .reg .u64 t; cvta.to.shared.u64 t, %1; cvt.u32.u64 %0, t; }" : "=r"(a) : "l"(p));
    return a;
}

#define STS128(a0, a1, a2, a3, addr) \
    asm volatile("st.shared.v4.b32 [%0], {%1, %2, %3, %4};" :: "r"(addr), "r"(a0), "r"(a1), "r"(a2), "r"(a3) : "memory")

#define LDSM2(r, addr) \
    asm volatile("ldmatrix.sync.aligned.m8n8.x2.shared.b16 {%0,%1}, [%2];" \
        : "=r"((r)[0]), "=r"((r)[1]) : "r"(addr))

#define MMA_F16(d, a, b) \
    asm volatile("mma.sync.aligned.m16n8k16.row.col.f32.f16.f16.f32 " \
        "{%0,%1,%2,%3}, {%4,%5,%6,%7}, {%8,%9}, {%0,%1,%2,%3};" \
        : "+f"((d)[0]), "+f"((d)[1]), "+f"((d)[2]), "+f"((d)[3]) \
        : "r"((a)[0]), "r"((a)[1]), "r"((a)[2]), "r"((a)[3]), "r"((b)[0]), "r"((b)[1]))

// W f16 tile layout: 64B rows, unit u (0..3, 16B), XOR swizzle. (verified R6+)
#define ASWZ64(r, u) ((uint32_t)((r) * 64 + (((u) ^ (((r) >> 1) & 3)) * 16)))

// pack two f32 -> f16x2 (x0 in low half)
__device__ __forceinline__ uint32_t cvt2h(float x0, float x1) {
    uint32_t r;
    asm("cvt.rn.f16x2.f32 %0, %1, %2;" : "=r"(r) : "f"(x1), "f"(x0));
    return r;
}

// ===========================================================================
// et GEMM: C[M,128] = A1[M,128k] @ W[0:128,:] + A2[M,128k] @ W[128:256,:] + be
// fp16 single-term mma.sync. 148 persistent CTAs x 512 threads (16 warps),
// warp grid 8(M) x 2(N): 32 rows x 64 cols per warp. M-tile 256, k16 steps.
//
// A path: NO shared memory for A. Each thread LDG.128s exactly the f32 its
// own MMA fragments need, cvt -> f16x2 in registers. This works because W is
// stored in smem with a PERMUTED k-order matching fragment positions:
//   frag pos p (0..15) holds actual k: p<8 -> (p/2)*4 + (p&1)
//                                      p>=8 -> ((p-8)/2)*4 + 2 + (p&1)
// so thread lane%4 reads the contiguous float4 at k = base + (lane&3)*4.
// The MMA dot-product is order-invariant over k, so results are identical.
//
// NO __syncthreads in the main loop: warps fully independent; tensor pipe
// never drains at chunk boundaries or epilogues.
//
// smem (66KB): [0..65536) W f16 (8 k32-chunks, ASWZ64), [65536..66048) bias.
// ===========================================================================
#define OFF_BIAS 65536
#define SMEM_ET  66048

__global__ __launch_bounds__(512, 1)
void et_mma_kernel(const float* __restrict__ A1,
                   const float* __restrict__ A2,
                   const float* __restrict__ W,     // [256,128] f32
                   const float* __restrict__ bias,  // [128]
                   float* __restrict__ C)           // [M,128]
{
    extern __shared__ char smem[];
    const uint32_t sb = smem_u32_of(smem);
    const int tid   = threadIdx.x;
    const int lane  = tid & 31;
    const int wid   = tid >> 5;
    const int warpM = wid >> 1;      // 0..7 -> rows warpM*32
    const int warpN = wid & 1;       // 0..1 -> cols warpN*64

    // ---- one-time W conversion: frag-ordered (permuted) k layout ----
    {
        const int n = tid & 127;
        const int g = tid >> 7;                 // 0..3
#pragma unroll
        for (int t = 0; t < 8; ++t) {
            const int kk = g * 8 + t;           // 16B-unit index 0..31
            const int c  = kk >> 2;             // k32 chunk
            const int u  = kk & 3;
            float w[8];
#pragma unroll
            for (int j = 0; j < 8; ++j) {
                const int p   = (u & 1) * 8 + j;    // frag position in k16
                const int akl = (p < 8) ? ((p >> 1) * 4 + (p & 1))
                                        : (((p - 8) >> 1) * 4 + 2 + (p & 1));
                const int kact = c * 32 + (u >> 1) * 16 + akl;
                w[j] = W[kact * 128 + n];
            }
            uint32_t p0 = cvt2h(w[0], w[1]);
            uint32_t p1 = cvt2h(w[2], w[3]);
            uint32_t p2 = cvt2h(w[4], w[5]);
            uint32_t p3 = cvt2h(w[6], w[7]);
            STS128(p0, p1, p2, p3, sb + c * 8192 + ASWZ64(n, u));
        }
        if (tid < 128) ((float*)(smem + OFF_BIAS))[tid] = bias[tid];
    }
    __syncthreads();

    // ---- invariants ----
    // B ldmatrix addressing (unchanged machinery from R6)
    const int ls = lane & 15;
    const int n0 = warpN * 64 + (ls & 7);
    const int ub = ls >> 3;
    const int xn = (n0 >> 1) & 3;
    uint32_t boffs[2];
#pragma unroll
    for (int s = 0; s < 2; ++s)
        boffs[s] = (uint32_t)(n0 * 64 + (((2 * s + ub) ^ xn) * 16));

    // A fragment addressing: rows rbase + mt*16 (+8), cols kbase + (lane&3)*4
    const int rbase = warpM * 32 + (lane >> 2);
    const int acol  = (lane & 3) << 2;
    const float* bias_s = (const float*)(smem + OFF_BIAS);

    int tile = blockIdx.x;

    // prefetch step (c=0, s=0) of first tile
    float4 pv[2][2];     // [mt][row half]
    if (tile < N_TILES2) {
#pragma unroll
        for (int mt = 0; mt < 2; ++mt) {
            const float* pr = A1 + (size_t)(tile * 256 + rbase + mt * 16) * 128 + acol;
            pv[mt][0] = *(const float4*)pr;
            pv[mt][1] = *(const float4*)(pr + 8 * 128);
        }
    }

    while (tile < N_TILES2) {
        float acc[2][8][4];
#pragma unroll
        for (int nt = 0; nt < 8; ++nt) {
            const float2 bb = *(const float2*)&bias_s[warpN * 64 + nt * 8 + (lane & 3) * 2];
#pragma unroll
            for (int mt = 0; mt < 2; ++mt) {
                acc[mt][nt][0] = bb.x; acc[mt][nt][1] = bb.y;
                acc[mt][nt][2] = bb.x; acc[mt][nt][3] = bb.y;
            }
        }

#pragma unroll 1
        for (int c = 0; c < 8; ++c) {
#pragma unroll
            for (int s = 0; s < 2; ++s) {
                // B fragments for this k16 step
                uint32_t Bv[8][2];
                const uint32_t wb = sb + (uint32_t)(c * 8192) + boffs[s];
#pragma unroll
                for (int nt = 0; nt < 8; ++nt) LDSM2(Bv[nt], wb + nt * 512);

                // next-step coordinates (wraps into next tile's step 0)
                int ntile = tile, nc = c, ns = s + 1;
                if (ns == 2) { ns = 0; if (++nc == 8) { nc = 0; ntile += gridDim.x; } }
                const float* nbase = (nc < 4) ? A1 : A2;
                const int    ncol  = (nc & 3) * 32 + ns * 16 + acol;
                const bool   valid = ntile < N_TILES2;

                // mt = 0: convert, refill prefetch, MMA
                {
                    uint32_t Af[4];
                    Af[0] = cvt2h(pv[0][0].x, pv[0][0].y);
                    Af[1] = cvt2h(pv[0][1].x, pv[0][1].y);
                    Af[2] = cvt2h(pv[0][0].z, pv[0][0].w);
                    Af[3] = cvt2h(pv[0][1].z, pv[0][1].w);
                    if (valid) {
                        const float* pr = nbase + (size_t)(ntile * 256 + rbase) * 128 + ncol;
                        pv[0][0] = *(const float4*)pr;
                        pv[0][1] = *(const float4*)(pr + 8 * 128);
                    }
#pragma unroll
                    for (int nt = 0; nt < 8; ++nt) MMA_F16(acc[0][nt], Af, Bv[nt]);
                }
                // mt = 1
                {
                    uint32_t Af[4];
                    Af[0] = cvt2h(pv[1][0].x, pv[1][0].y);
                    Af[1] = cvt2h(pv[1][1].x, pv[1][1].y);
                    Af[2] = cvt2h(pv[1][0].z, pv[1][0].w);
                    Af[3] = cvt2h(pv[1][1].z, pv[1][1].w);
                    if (valid) {
                        const float* pr = nbase + (size_t)(ntile * 256 + rbase + 16) * 128 + ncol;
                        pv[1][0] = *(const float4*)pr;
                        pv[1][1] = *(const float4*)(pr + 8 * 128);
                    }
#pragma unroll
                    for (int nt = 0; nt < 8; ++nt) MMA_F16(acc[1][nt], Af, Bv[nt]);
                }
            }
        }

        // epilogue: direct STG (32B-sector aligned float2 stores); no barrier
        const size_t m0 = (size_t)tile * 256;
#pragma unroll
        for (int mt = 0; mt < 2; ++mt) {
            const size_t r0 = m0 + warpM * 32 + mt * 16 + (lane >> 2);
#pragma unroll
            for (int nt = 0; nt < 8; ++nt) {
                const int col = warpN * 64 + nt * 8 + (lane & 3) * 2;
                *(float2*)&C[r0 * 128 + col]       = make_float2(acc[mt][nt][0], acc[mt][nt][1]);
                *(float2*)&C[(r0 + 8) * 128 + col] = make_float2(acc[mt][nt][2], acc[mt][nt][3]);
            }
        }
        tile += gridDim.x;
    }
}

// ===========================================================================
// Kernel 2: msg1/msg2/o1 = nt @ {W_m1,W_m2,W_o1} + bias.
// ===========================================================================
__global__ __launch_bounds__(512)
void msgs_gemm_kernel(const float* __restrict__ node,
                      const float* __restrict__ hidden,
                      const float* __restrict__ Wm1, const float* __restrict__ bm1,
                      const float* __restrict__ Wm2, const float* __restrict__ bm2,
                      const float* __restrict__ Wo1, const float* __restrict__ bo1)
{
    __shared__ float s[8][2 * Ff];
    __shared__ float part[3][3][8][128];
    const int r0  = blockIdx.x * 8;
    const int tid = threadIdx.x;
    const int col = tid & 127;
    const int kq  = tid >> 7;

    for (int t = tid; t < 8 * 256; t += 512) {
        const int r = t >> 8, k = t & 255;
        const int rowi = r0 + r;
        const int b = rowi / (Nn + 1);
        const int i = rowi % (Nn + 1);
        float v = 0.f;
        if (i < Nn)
            v = (k < Ff) ? node[(b * Nn + i) * Ff + k]
                         : hidden[(b * Nn + i) * Ff + (k - Ff)];
        s[r][k] = v;
    }
    __syncthreads();

    float a1[8], a2[8], a3[8];
#pragma unroll
    for (int r = 0; r < 8; ++r) { a1[r] = 0.f; a2[r] = 0.f; a3[r] = 0.f; }

    const int kbase = kq * 64;
#pragma unroll 4
    for (int kk = 0; kk < 64; ++kk) {
        const int k = kbase + kk;
        const float w1 = Wm1[k * Dd + col];
        const float w2 = Wm2[k * Dd + col];
        const float w3 = Wo1[k * Dd + col];
#pragma unroll
        for (int r = 0; r < 8; ++r) {
            const float sv = s[r][k];
            a1[r] = fmaf(sv, w1, a1[r]);
            a2[r] = fmaf(sv, w2, a2[r]);
            a3[r] = fmaf(sv, w3, a3[r]);
        }
    }

    if (kq) {
#pragma unroll
        for (int r = 0; r < 8; ++r) {
            part[kq - 1][0][r][col] = a1[r];
            part[kq - 1][1][r][col] = a2[r];
            part[kq - 1][2][r][col] = a3[r];
        }
    }
    __syncthreads();

    if (kq == 0) {
        const float bb1 = bm1[col], bb2 = bm2[col], bb3 = bo1[col];
#pragma unroll
        for (int r = 0; r < 8; ++r) {
            float o1 = a1[r] + bb1, o2 = a2[r] + bb2, o3 = a3[r] + bb3;
#pragma unroll
            for (int q = 0; q < 3; ++q) {
                o1 += part[q][0][r][col];
                o2 += part[q][1][r][col];
                o3 += part[q][2][r][col];
            }
            const int rowi = r0 + r;
            g_msg1[rowi * Dd + col] = o1;
            g_msg2[rowi * Dd + col] = o2;
            g_o1[rowi * Dd + col]   = o3;
        }
    }
}

// ===========================================================================
// Kernel 3 (fused): masked max + add msg1, then ret = o1 + msgs @ W_o2 + b_o2
// ===========================================================================
__global__ __launch_bounds__(256)
void maxfinal_kernel(const int* __restrict__ adj,
                     const float* __restrict__ Wo2,
                     const float* __restrict__ bo2,
                     float* __restrict__ out)      // [B*N,128]
{
    __shared__ int mask[Nn];
    __shared__ float red[2][4][128];
    __shared__ float ms[4][128];
    __shared__ float pg[4][128];
    const int blk = blockIdx.x;
    const int b   = blk >> 6;
    const int j0  = (blk & 63) * 4;
    const int tid = threadIdx.x;
    const int d   = tid & 127;
    const int ih  = tid >> 7;

    {
        const int* p = adj + ((size_t)(b * Nn + tid) * Nn + j0);
        const int4 a = *(const int4*)p;
        mask[tid] = (a.x > 0) | ((a.y > 0) << 1) | ((a.z > 0) << 2) | ((a.w > 0) << 3);
    }
    __syncthreads();

    const float* m2 = g_msg2 + (size_t)(b * (Nn + 1)) * Dd + d;
    const float vv = m2[Nn * Dd];
    float vj[4] = {vv, vv, vv, vv};

#pragma unroll 4
    for (int ii = 0; ii < 128; ++ii) {
        const int i = ih * 128 + ii;
        const float x = m2[i * Dd];
        const int mk = mask[i];
#pragma unroll
        for (int q = 0; q < 4; ++q)
            if (mk & (1 << q)) vj[q] = fmaxf(vj[q], x);
    }
#pragma unroll
    for (int q = 0; q < 4; ++q) red[ih][q][d] = vj[q];
    __syncthreads();

    if (ih == 0) {
#pragma unroll
        for (int q = 0; q < 4; ++q)
            ms[q][d] = g_msg1[(size_t)(b * (Nn + 1) + j0 + q) * Dd + d]
                     + fmaxf(red[0][q][d], red[1][q][d]);
    }
    __syncthreads();

    float acc[4] = {0.f, 0.f, 0.f, 0.f};
    const int kb = ih * 64;
#pragma unroll 4
    for (int kk = 0; kk < 64; ++kk) {
        const int k = kb + kk;
        const float w = Wo2[k * Dd + d];
#pragma unroll
        for (int q = 0; q < 4; ++q) acc[q] = fmaf(ms[q][k], w, acc[q]);
    }
    if (ih) {
#pragma unroll
        for (int q = 0; q < 4; ++q) pg[q][d] = acc[q];
    }
    __syncthreads();
    if (!ih) {
        const float bb = bo2[d];
#pragma unroll
        for (int q = 0; q < 4; ++q)
            out[(size_t)(b * Nn + j0 + q) * Dd + d] =
                acc[q] + pg[q][d] + g_o1[(size_t)(b * (Nn + 1) + j0 + q) * Dd + d] + bb;
    }
}

// ===========================================================================
extern "C" void kernel_launch(void* const* d_in, const int* in_sizes, int n_in,
                              void* d_out, int out_size)
{
    const float* node_fts = (const float*)d_in[0];
    const float* edge_fts = (const float*)d_in[1];
    const int*   adj_mat  = (const int*)d_in[3];
    const float* hidden   = (const float*)d_in[4];
    const float* e_hidden = (const float*)d_in[5];
    const float* We   = (const float*)d_in[6];
    const float* be   = (const float*)d_in[7];
    const float* W_m1 = (const float*)d_in[8];
    const float* b_m1 = (const float*)d_in[9];
    const float* W_m2 = (const float*)d_in[10];
    const float* b_m2 = (const float*)d_in[11];
    const float* W_o1 = (const float*)d_in[12];
    const float* b_o1 = (const float*)d_in[13];
    const float* W_o2 = (const float*)d_in[14];
    const float* b_o2 = (const float*)d_in[15];

    float* ret_out = (float*)d_out;
    float* et_out  = (float*)d_out + Bq * Nn * Dd;

    static cudaStream_t s_chain = nullptr;
    static cudaEvent_t ev_fork = nullptr, ev_join = nullptr;
    if (!s_chain) {
        cudaStreamCreateWithFlags(&s_chain, cudaStreamNonBlocking);
        cudaEventCreateWithFlags(&ev_fork, cudaEventDisableTiming);
        cudaEventCreateWithFlags(&ev_join, cudaEventDisableTiming);
        cudaFuncSetAttribute(et_mma_kernel, cudaFuncAttributeMaxDynamicSharedMemorySize, SMEM_ET);
    }

    // fork: MPNN chain runs concurrently with the big et GEMM
    cudaEventRecord(ev_fork, 0);
    cudaStreamWaitEvent(s_chain, ev_fork, 0);
    msgs_gemm_kernel<<<NROWS / 8, 512, 0, s_chain>>>(node_fts, hidden,
                                                     W_m1, b_m1, W_m2, b_m2, W_o1, b_o1);
    maxfinal_kernel<<<Bq * Nn / 4, 256, 0, s_chain>>>(adj_mat, W_o2, b_o2, ret_out);
    cudaEventRecord(ev_join, s_chain);

    // et GEMM (barrier-free A-in-register fp16 mma, W resident in smem)
    et_mma_kernel<<<148, 512, SMEM_ET>>>(edge_fts, e_hidden, We, be, et_out);

    // join
    cudaStreamWaitEvent(0, ev_join, 0);
}